// round 12
// baseline (speedup 1.0000x reference)
#include <cuda_runtime.h>
#include <cuda_bf16.h>
#include <math_constants.h>

// Problem constants (fixed by setup_inputs)
#define B_   4
#define N_   8192
#define BN_  (B_ * N_)      // 32768 points
#define DIN  64
#define DPRE 67             // feature(64) + xyz(3)
#define C_   128            // D_OUT
#define K_   36

// spatial grid
#define G_   16
#define GC_  (G_ * G_ * G_)   // 4096 cells per batch

// ---------------- device scratch (no allocations allowed) ----------------
__device__ float  g_EP [BN_ * C_];   // exp(Wr_left @ pre)           (sorted order)
__device__ float  g_EQ [BN_ * C_];   // exp((Wr_r - Wr_l) @ pre + br)(sorted order)
__device__ float  g_V  [BN_ * C_];   // relu(Wv @ pre + bv)          (sorted order)
__device__ float  g_mid[BN_ * C_];   // attention output             (sorted order)
__device__ int    g_nbr[BN_ * K_];   // knn neighbor SORTED positions
__device__ int    g_cellcnt [B_ * GC_];
__device__ int    g_cellstart[B_ * GC_];
__device__ float4 g_pts4 [BN_];      // sorted points (x,y,z,pad)
__device__ int    g_pid  [BN_];      // sorted pos -> original global id
__device__ int    g_spos [BN_];      // original global id -> sorted pos

// ---------------- fast exp (FMA pipe) ------------------------------------
__device__ __forceinline__ float fast_exp(float x) {
    float y = x * 1.4426950408889634f;      // x * log2(e)
    int   e = __float2int_rn(y);
    float f = y - (float)e;                 // f in [-0.5, 0.5]
    float p =            1.5403530393381609e-4f;
    p = fmaf(p, f, 1.3333558146428443e-3f);
    p = fmaf(p, f, 9.6181291076284770e-3f);
    p = fmaf(p, f, 5.5504108664821580e-2f);
    p = fmaf(p, f, 2.4022650695910070e-1f);
    p = fmaf(p, f, 6.9314718055994530e-1f);
    p = fmaf(p, f, 1.0f);
    float s = __int_as_float((e + 127) << 23);
    return p * s;
}

// ============================================================================
// FUSED grid build, one block per batch (1024 threads).
//  phase 1: smem counting
//  phase 2: shfl exclusive scan over 4096 cells; publish cnt/start
//  phase 3: scatter batch-local pids into smem (atomic cursors)
//  phase 4: per-cell insertion sort of pids IN SMEM (cheap LDS, not gmem),
//           then emit g_pid/g_spos and rebuild g_pts4 from xyz (L2-hot).
// Layout is bit-identical to the unfused pipeline (sort canonicalizes order).
// ============================================================================
#define BUILD_SMEM ((GC_ + GC_ + N_ + 32) * 4)

__global__ __launch_bounds__(1024) void build_kernel(const float* __restrict__ xyz) {
    extern __shared__ int sb[];
    int* scnt   = sb;                 // [GC_] counts -> cursors
    int* sstart = sb + GC_;           // [GC_]
    int* spid   = sb + 2 * GC_;       // [N_] batch-local pids, cell-grouped
    int* wsum   = sb + 2 * GC_ + N_;  // [32]

    int b = blockIdx.x;
    int t = threadIdx.x, lane = t & 31, w = t >> 5;

    for (int i = t; i < GC_; i += 1024) scnt[i] = 0;
    __syncthreads();

    // phase 1
    int mycell[8];
    #pragma unroll
    for (int s = 0; s < 8; s++) {
        int ml = s * 1024 + t;
        const float* p = xyz + ((size_t)b * N_ + ml) * 3;
        int cx = min(G_ - 1, max(0, (int)(p[0] * (float)G_)));
        int cy = min(G_ - 1, max(0, (int)(p[1] * (float)G_)));
        int cz = min(G_ - 1, max(0, (int)(p[2] * (float)G_)));
        int cell = (cx * G_ + cy) * G_ + cz;
        mycell[s] = cell;
        atomicAdd(&scnt[cell], 1);
    }
    __syncthreads();

    // phase 2: exclusive scan (4 cells/thread)
    int c0 = scnt[4 * t + 0], c1 = scnt[4 * t + 1];
    int c2 = scnt[4 * t + 2], c3 = scnt[4 * t + 3];
    int tot = c0 + c1 + c2 + c3;
    int incl = tot;
    #pragma unroll
    for (int off = 1; off < 32; off <<= 1) {
        int v = __shfl_up_sync(0xffffffffu, incl, off);
        if (lane >= off) incl += v;
    }
    if (lane == 31) wsum[w] = incl;
    __syncthreads();
    if (w == 0) {
        int v = wsum[lane];
        #pragma unroll
        for (int off = 1; off < 32; off <<= 1) {
            int u = __shfl_up_sync(0xffffffffu, v, off);
            if (lane >= off) v += u;
        }
        wsum[lane] = v;
    }
    __syncthreads();
    int excl = incl - tot + (w > 0 ? wsum[w - 1] : 0);
    int st0 = excl, st1 = excl + c0, st2 = excl + c0 + c1, st3 = excl + c0 + c1 + c2;
    sstart[4 * t + 0] = st0;  sstart[4 * t + 1] = st1;
    sstart[4 * t + 2] = st2;  sstart[4 * t + 3] = st3;
    g_cellcnt [b * GC_ + 4 * t + 0] = c0;  g_cellcnt [b * GC_ + 4 * t + 1] = c1;
    g_cellcnt [b * GC_ + 4 * t + 2] = c2;  g_cellcnt [b * GC_ + 4 * t + 3] = c3;
    g_cellstart[b * GC_ + 4 * t + 0] = st0; g_cellstart[b * GC_ + 4 * t + 1] = st1;
    g_cellstart[b * GC_ + 4 * t + 2] = st2; g_cellstart[b * GC_ + 4 * t + 3] = st3;
    __syncthreads();

    // reuse scnt as cursor
    scnt[4 * t + 0] = st0; scnt[4 * t + 1] = st1;
    scnt[4 * t + 2] = st2; scnt[4 * t + 3] = st3;
    __syncthreads();

    // phase 3: scatter pids into smem
    #pragma unroll
    for (int s = 0; s < 8; s++) {
        int ml = s * 1024 + t;
        int r = atomicAdd(&scnt[mycell[s]], 1);
        spid[r] = ml;
    }
    __syncthreads();

    // phase 4: per-cell smem insertion sort + emit
    #pragma unroll
    for (int cc = 0; cc < 4; cc++) {
        int cell = 4 * t + cc;
        int start = sstart[cell];
        int end   = scnt[cell];             // cursor ended at start+cnt
        for (int a = start + 1; a < end; a++) {
            int pid = spid[a];
            int j = a - 1;
            while (j >= start && spid[j] > pid) { spid[j + 1] = spid[j]; j--; }
            spid[j + 1] = pid;
        }
        for (int a = start; a < end; a++) {
            int pid = spid[a];                       // batch-local
            int gp  = b * N_ + a;                    // sorted global pos
            const float* p = xyz + ((size_t)b * N_ + pid) * 3;
            g_pts4[gp] = make_float4(p[0], p[1], p[2], 0.0f);
            g_pid[gp]  = b * N_ + pid;
            g_spos[b * N_ + pid] = gp;
        }
    }
}

// ============================================================================
// Kernel: per-point preprocessing (EP/EQ/V), written in SORTED order for the
// attention gather's locality. Weights staged in smem transposed to [d][c].
// Takes a block offset so it can be launched as two half-grids.
// ============================================================================
#define PREP_SMEM ((3 * DPRE * C_ + 4 * 4 * 68) * 4)

__global__ void prep_kernel(const float* __restrict__ feat,
                            const float* __restrict__ xyz,
                            const float* __restrict__ Wr,
                            const float* __restrict__ br,
                            const float* __restrict__ Wv,
                            const float* __restrict__ bv,
                            int blk0) {
    extern __shared__ float sm[];
    float* sWA = sm;                       // Wr_left   [d][c]
    float* sWB = sm + DPRE * C_;           // Wr_right  [d][c] (then -= left)
    float* sWC = sm + 2 * DPRE * C_;       // Wv        [d][c]
    float* sPre = sm + 3 * DPRE * C_;      // [warp][4][68]

    int t = threadIdx.x;
    for (int i = t; i < C_ * 134; i += 128) {
        int c = i / 134, dd = i % 134;
        float v = Wr[i];
        if (dd < DPRE) sWA[dd * C_ + c] = v;
        else           sWB[(dd - DPRE) * C_ + c] = v;
    }
    for (int i = t; i < C_ * DPRE; i += 128) {
        int c = i / DPRE, d = i % DPRE;
        sWC[d * C_ + c] = Wv[i];
    }
    __syncthreads();
    for (int i = t; i < DPRE * C_; i += 128) sWB[i] -= sWA[i];
    __syncthreads();

    int w = t >> 5, lane = t & 31;
    float4 br4 = *(const float4*)&br[4 * lane];
    float4 bv4 = *(const float4*)&bv[4 * lane];
    float* spw = sPre + w * 4 * 68;

    int base = (blk0 + blockIdx.x) * 128 + w * 32;   // 32 points per warp
    for (int it = 0; it < 8; it++) {
        int m0 = base + it * 4;
        #pragma unroll
        for (int p = 0; p < 4; p++) {
            int m = m0 + p;
            spw[p * 68 + lane]      = feat[(size_t)m * 64 + lane];
            spw[p * 68 + 32 + lane] = feat[(size_t)m * 64 + 32 + lane];
            if (lane < 3) spw[p * 68 + 64 + lane] = xyz[(size_t)m * 3 + lane];
        }
        __syncwarp();

        float aP[4][4], aQ[4][4], aV[4][4];
        #pragma unroll
        for (int p = 0; p < 4; p++)
            #pragma unroll
            for (int r = 0; r < 4; r++) { aP[p][r] = 0.f; aQ[p][r] = 0.f; aV[p][r] = 0.f; }

        for (int d = 0; d < DPRE; d++) {
            float4 wa = *(float4*)&sWA[d * C_ + 4 * lane];
            float4 wb = *(float4*)&sWB[d * C_ + 4 * lane];
            float4 wc = *(float4*)&sWC[d * C_ + 4 * lane];
            #pragma unroll
            for (int p = 0; p < 4; p++) {
                float x = spw[p * 68 + d];
                aP[p][0] = fmaf(wa.x, x, aP[p][0]);
                aP[p][1] = fmaf(wa.y, x, aP[p][1]);
                aP[p][2] = fmaf(wa.z, x, aP[p][2]);
                aP[p][3] = fmaf(wa.w, x, aP[p][3]);
                aQ[p][0] = fmaf(wb.x, x, aQ[p][0]);
                aQ[p][1] = fmaf(wb.y, x, aQ[p][1]);
                aQ[p][2] = fmaf(wb.z, x, aQ[p][2]);
                aQ[p][3] = fmaf(wb.w, x, aQ[p][3]);
                aV[p][0] = fmaf(wc.x, x, aV[p][0]);
                aV[p][1] = fmaf(wc.y, x, aV[p][1]);
                aV[p][2] = fmaf(wc.z, x, aV[p][2]);
                aV[p][3] = fmaf(wc.w, x, aV[p][3]);
            }
        }
        #pragma unroll
        for (int p = 0; p < 4; p++) {
            size_t sp = (size_t)g_spos[m0 + p];     // sorted destination
            float4 ep, eq, vv;
            ep.x = fast_exp(aP[p][0]); ep.y = fast_exp(aP[p][1]);
            ep.z = fast_exp(aP[p][2]); ep.w = fast_exp(aP[p][3]);
            eq.x = fast_exp(aQ[p][0] + br4.x); eq.y = fast_exp(aQ[p][1] + br4.y);
            eq.z = fast_exp(aQ[p][2] + br4.z); eq.w = fast_exp(aQ[p][3] + br4.w);
            vv.x = fmaxf(aV[p][0] + bv4.x, 0.f); vv.y = fmaxf(aV[p][1] + bv4.y, 0.f);
            vv.z = fmaxf(aV[p][2] + bv4.z, 0.f); vv.w = fmaxf(aV[p][3] + bv4.w, 0.f);
            *(float4*)&g_EP[sp * C_ + 4 * lane] = ep;
            *(float4*)&g_EQ[sp * C_ + 4 * lane] = eq;
            *(float4*)&g_V [sp * C_ + 4 * lane] = vv;
        }
        __syncwarp();
    }
}

// ============================================================================
// Kernel: exact 36-NN, WARP PER QUERY, wall-aware initial radius.
// Register top-10 per lane; 36-count certificate for exactness; warp
// extract-min merge (deterministic given the sorted, canonical layout).
// ============================================================================
#define LLEN 10
#define INFBITS 0x7f800000u
#define EXHBITS 0xffffffffu

__global__ void knnq_kernel() {
    int lane = threadIdx.x & 31;
    int q = blockIdx.x * (blockDim.x >> 5) + (threadIdx.x >> 5);  // sorted pos
    int b = q >> 13;

    float4 me = g_pts4[q];
    float qx = me.x, qy = me.y, qz = me.z;
    int cx = min(G_ - 1, max(0, (int)(qx * (float)G_)));
    int cy = min(G_ - 1, max(0, (int)(qy * (float)G_)));
    int cz = min(G_ - 1, max(0, (int)(qz * (float)G_)));

    const float h = 1.0f / (float)G_;
    const int cbase = b * GC_;
    const int pbase = b * N_;

    int clip = ((cx < 2 || cx > G_ - 3) ? 1 : 0)
             + ((cy < 2 || cy > G_ - 3) ? 1 : 0)
             + ((cz < 2 || cz > G_ - 3) ? 1 : 0);
    int r0 = 2 + clip;

    unsigned ld[LLEN];
    int      lp[LLEN];

    for (int r = r0; ; r++) {
        #pragma unroll
        for (int s = 0; s < LLEN; s++) { ld[s] = INFBITS; lp[s] = -1; }

        int lox = max(cx - r, 0), hix = min(cx + r, G_ - 1);
        int loy = max(cy - r, 0), hiy = min(cy + r, G_ - 1);
        int loz = max(cz - r, 0), hiz = min(cz + r, G_ - 1);

        float d1 = (lox > 0)      ? (qx - (float)lox * h)        : 1e9f;
        float d2 = (hix < G_ - 1) ? ((float)(hix + 1) * h - qx)  : 1e9f;
        float d3 = (loy > 0)      ? (qy - (float)loy * h)        : 1e9f;
        float d4 = (hiy < G_ - 1) ? ((float)(hiy + 1) * h - qy)  : 1e9f;
        float d5 = (loz > 0)      ? (qz - (float)loz * h)        : 1e9f;
        float d6 = (hiz < G_ - 1) ? ((float)(hiz + 1) * h - qz)  : 1e9f;
        float dmin = fminf(fminf(fminf(d1, d2), fminf(d3, d4)), fminf(d5, d6));
        float dth = fminf(dmin * dmin, 1e9f);

        int cnt_near = 0;
        int streamoff = 0;

        for (int ix = lox; ix <= hix; ix++) {
            for (int iy = loy; iy <= hiy; iy++) {
                int col = (ix * G_ + iy) * G_;
                int s0  = g_cellstart[cbase + col + loz];
                int e0  = g_cellstart[cbase + col + hiz] + g_cellcnt[cbase + col + hiz];
                int len = e0 - s0;
                int base = pbase + s0;
                for (int j = (lane - streamoff) & 31; j < len; j += 32) {
                    float4 c = g_pts4[base + j];
                    float dx = c.x - qx, dy = c.y - qy, dz = c.z - qz;
                    float d = fmaf(dz, dz, fmaf(dy, dy, dx * dx));
                    cnt_near += (d <= dth) ? 1 : 0;
                    unsigned db = __float_as_uint(d);
                    if (db < ld[LLEN - 1]) {
                        unsigned cd = db; int cp = base + j;
                        #pragma unroll
                        for (int s = 0; s < LLEN; s++) {
                            unsigned od = ld[s]; int op = lp[s];
                            if (cd < od) { ld[s] = cd; lp[s] = cp; cd = od; cp = op; }
                        }
                    }
                }
                streamoff += len;
            }
        }

        unsigned tot = __reduce_add_sync(0xffffffffu, (unsigned)cnt_near);
        bool all = (lox == 0 && hix == G_ - 1 && loy == 0 && hiy == G_ - 1 &&
                    loz == 0 && hiz == G_ - 1);
        if (tot >= (unsigned)K_ || all) break;
    }

    for (int s = 0; s < K_; s++) {
        unsigned myh = ld[0];
        unsigned m = __reduce_min_sync(0xffffffffu, myh);
        unsigned mask = __ballot_sync(0xffffffffu, myh == m);
        int leader = __ffs(mask) - 1;
        if (lane == leader) {
            g_nbr[(size_t)q * K_ + s] = lp[0];
            #pragma unroll
            for (int t2 = 0; t2 < LLEN - 1; t2++) { ld[t2] = ld[t2 + 1]; lp[t2] = lp[t2 + 1]; }
            ld[LLEN - 1] = EXHBITS;
        }
    }
}

// ============================================================================
// Kernel: vector attention accumulate. Warp per query; 512-thread blocks so
// 16 spatially-adjacent queries share L1 for the gathered EP/V rows.
// ============================================================================
__global__ void attn_kernel() {
    int gw   = (blockIdx.x * blockDim.x + threadIdx.x) >> 5;
    int lane = threadIdx.x & 31;
    if (gw >= BN_) return;
    size_t q = (size_t)gw;

    float4 eq = *(const float4*)&g_EQ[q * C_ + 4 * lane];
    int i0 = g_nbr[q * K_ + lane];
    int i1 = (lane < K_ - 32) ? g_nbr[q * K_ + 32 + lane] : 0;

    float4 acc = make_float4(0.f, 0.f, 0.f, 0.f);
    #pragma unroll 4
    for (int k = 0; k < K_; k++) {
        int j = (k < 32) ? __shfl_sync(0xffffffffu, i0, k)
                         : __shfl_sync(0xffffffffu, i1, k - 32);
        float4 ep = *(const float4*)&g_EP[(size_t)j * C_ + 4 * lane];
        float4 v  = *(const float4*)&g_V [(size_t)j * C_ + 4 * lane];
        float wx = ep.x * eq.x, wy = ep.y * eq.y, wz = ep.z * eq.z, ww = ep.w * eq.w;
        float part = (wx + wy) + (wz + ww);
        part += __shfl_xor_sync(0xffffffffu, part, 16);
        part += __shfl_xor_sync(0xffffffffu, part, 8);
        part += __shfl_xor_sync(0xffffffffu, part, 4);
        part += __shfl_xor_sync(0xffffffffu, part, 2);
        part += __shfl_xor_sync(0xffffffffu, part, 1);
        float rinv = __fdividef(1.0f, part);
        acc.x = fmaf(v.x, wx * rinv, acc.x);
        acc.y = fmaf(v.y, wy * rinv, acc.y);
        acc.z = fmaf(v.z, wz * rinv, acc.z);
        acc.w = fmaf(v.w, ww * rinv, acc.w);
    }
    *(float4*)&g_mid[q * C_ + 4 * lane] = acc;
}

// ============================================================================
// Kernel: output projection  out[pid[q]] = mid[q] @ Ws^T + bs.
// ============================================================================
#define WS_STRIDE 132
#define OUT_SMEM  ((C_ * WS_STRIDE + 8 * C_ * 9) * 4)

__global__ void outproj_kernel(const float* __restrict__ Ws,
                               const float* __restrict__ bs,
                               float* __restrict__ out) {
    extern __shared__ float sm[];
    float* sWs  = sm;                    // [c][d] stride WS_STRIDE
    float* sMid = sm + C_ * WS_STRIDE;   // [warp][c][9]

    int t = threadIdx.x, w = t >> 5, lane = t & 31;
    for (int i = t; i < C_ * C_; i += 256) {
        int d = i >> 7, c = i & 127;
        sWs[c * WS_STRIDE + d] = Ws[i];
    }
    __syncthreads();

    float4 bs4 = *(const float4*)&bs[4 * lane];
    float* smw = sMid + w * C_ * 9;
    int gw = blockIdx.x * 8 + w;                 // 4096 warps total
    int q0 = gw * 8;

    #pragma unroll
    for (int p = 0; p < 8; p++) {
        float4 m4 = *(const float4*)&g_mid[(size_t)(q0 + p) * C_ + 4 * lane];
        smw[(4 * lane + 0) * 9 + p] = m4.x;
        smw[(4 * lane + 1) * 9 + p] = m4.y;
        smw[(4 * lane + 2) * 9 + p] = m4.z;
        smw[(4 * lane + 3) * 9 + p] = m4.w;
    }
    __syncwarp();
    float4 acc[8];
    #pragma unroll
    for (int p = 0; p < 8; p++) acc[p] = bs4;
    for (int c = 0; c < C_; c++) {
        float4 wr = *(float4*)&sWs[c * WS_STRIDE + 4 * lane];
        #pragma unroll
        for (int p = 0; p < 8; p++) {
            float mc = smw[c * 9 + p];
            acc[p].x = fmaf(wr.x, mc, acc[p].x);
            acc[p].y = fmaf(wr.y, mc, acc[p].y);
            acc[p].z = fmaf(wr.z, mc, acc[p].z);
            acc[p].w = fmaf(wr.w, mc, acc[p].w);
        }
    }
    #pragma unroll
    for (int p = 0; p < 8; p++) {
        size_t row = (size_t)g_pid[q0 + p];     // back to original order
        *(float4*)&out[row * C_ + 4 * lane] = acc[p];
    }
}

// ============================================================================
extern "C" void kernel_launch(void* const* d_in, const int* in_sizes, int n_in,
                              void* d_out, int out_size) {
    const float* feat = (const float*)d_in[0];
    const float* xyz  = (const float*)d_in[1];
    const float* Wr   = (const float*)d_in[2];
    const float* br   = (const float*)d_in[3];
    const float* Wv   = (const float*)d_in[4];
    const float* bv   = (const float*)d_in[5];
    const float* Ws   = (const float*)d_in[6];
    const float* bs   = (const float*)d_in[7];
    float* out = (float*)d_out;

    cudaFuncSetAttribute(build_kernel, cudaFuncAttributeMaxDynamicSharedMemorySize, BUILD_SMEM);
    cudaFuncSetAttribute(prep_kernel, cudaFuncAttributeMaxDynamicSharedMemorySize, PREP_SMEM);
    cudaFuncSetAttribute(outproj_kernel, cudaFuncAttributeMaxDynamicSharedMemorySize, OUT_SMEM);

    // (0) fused grid build (counts/scan/scatter/smem-sort in one launch)
    build_kernel<<<B_, 1024, BUILD_SMEM>>>(xyz);

    // (1,2) per-point EP/EQ/V (two half-grids; identical math)
    prep_kernel<<<128, 128, PREP_SMEM>>>(feat, xyz, Wr, br, Wv, bv, 0);
    prep_kernel<<<128, 128, PREP_SMEM>>>(feat, xyz, Wr, br, Wv, bv, 128);

    // (3) exact 36-NN, warp per query   <-- ncu capture slot (launch index 3)
    knnq_kernel<<<BN_ / 8, 256>>>();

    // (4) vector attention accumulate
    attn_kernel<<<BN_ / 16, 512>>>();

    // (5) output projection (+ scatter back to original order)
    outproj_kernel<<<512, 256, OUT_SMEM>>>(Ws, bs, out);
}

// round 13
// speedup vs baseline: 1.2866x; 1.2866x over previous
#include <cuda_runtime.h>
#include <cuda_bf16.h>
#include <math_constants.h>

// Problem constants (fixed by setup_inputs)
#define B_   4
#define N_   8192
#define BN_  (B_ * N_)      // 32768 points
#define DIN  64
#define DPRE 67             // feature(64) + xyz(3)
#define C_   128            // D_OUT
#define K_   36

// spatial grid
#define G_   16
#define GC_  (G_ * G_ * G_)   // 4096 cells per batch

// ---------------- device scratch (no allocations allowed) ----------------
__device__ float  g_EP [BN_ * C_];   // exp(Wr_left @ pre)           (sorted order)
__device__ float  g_EQ [BN_ * C_];   // exp((Wr_r - Wr_l) @ pre + br)(sorted order)
__device__ float  g_V  [BN_ * C_];   // relu(Wv @ pre + bv)          (sorted order)
__device__ float  g_mid[BN_ * C_];   // attention output             (sorted order)
__device__ int    g_nbr[BN_ * K_];   // knn neighbor SORTED positions
__device__ int    g_cellcnt [B_ * GC_];
__device__ int    g_cellstart[B_ * GC_];
__device__ int    g_cellid[BN_];     // per original point: within-batch cell
__device__ int    g_rank  [BN_];     // atomic rank within cell (pre-sort)
__device__ float4 g_pts4 [BN_];      // sorted points (x,y,z,pad)
__device__ int    g_pid  [BN_];      // sorted pos -> original global id
__device__ int    g_spos [BN_];      // original global id -> sorted pos

// ---------------- fast exp (FMA pipe) ------------------------------------
__device__ __forceinline__ float fast_exp(float x) {
    float y = x * 1.4426950408889634f;      // x * log2(e)
    int   e = __float2int_rn(y);
    float f = y - (float)e;                 // f in [-0.5, 0.5]
    float p =            1.5403530393381609e-4f;
    p = fmaf(p, f, 1.3333558146428443e-3f);
    p = fmaf(p, f, 9.6181291076284770e-3f);
    p = fmaf(p, f, 5.5504108664821580e-2f);
    p = fmaf(p, f, 2.4022650695910070e-1f);
    p = fmaf(p, f, 6.9314718055994530e-1f);
    p = fmaf(p, f, 1.0f);
    float s = __int_as_float((e + 127) << 23);
    return p * s;
}

// ============================================================================
// Grid build (R5 pipeline — proven fastest config)
// ============================================================================
__global__ void cellassign_kernel(const float* __restrict__ xyz) {
    int m = blockIdx.x * blockDim.x + threadIdx.x;
    if (m >= BN_) return;
    int b = m >> 13;
    float x = xyz[(size_t)m * 3 + 0];
    float y = xyz[(size_t)m * 3 + 1];
    float z = xyz[(size_t)m * 3 + 2];
    int cx = min(G_ - 1, max(0, (int)(x * (float)G_)));
    int cy = min(G_ - 1, max(0, (int)(y * (float)G_)));
    int cz = min(G_ - 1, max(0, (int)(z * (float)G_)));
    int cell = (cx * G_ + cy) * G_ + cz;
    int r = atomicAdd(&g_cellcnt[b * GC_ + cell], 1);
    g_cellid[m] = cell;
    g_rank[m] = r;
}

__global__ void scan_kernel() {
    __shared__ int s[1024];
    int b = blockIdx.x;
    int t = threadIdx.x;
    int c0 = g_cellcnt[b * GC_ + 4 * t + 0];
    int c1 = g_cellcnt[b * GC_ + 4 * t + 1];
    int c2 = g_cellcnt[b * GC_ + 4 * t + 2];
    int c3 = g_cellcnt[b * GC_ + 4 * t + 3];
    int tot = c0 + c1 + c2 + c3;
    s[t] = tot;
    __syncthreads();
    for (int off = 1; off < 1024; off <<= 1) {
        int x = (t >= off) ? s[t - off] : 0;
        __syncthreads();
        s[t] += x;
        __syncthreads();
    }
    int excl = s[t] - tot;
    g_cellstart[b * GC_ + 4 * t + 0] = excl;
    g_cellstart[b * GC_ + 4 * t + 1] = excl + c0;
    g_cellstart[b * GC_ + 4 * t + 2] = excl + c0 + c1;
    g_cellstart[b * GC_ + 4 * t + 3] = excl + c0 + c1 + c2;
}

__global__ void scatter_kernel(const float* __restrict__ xyz) {
    int m = blockIdx.x * blockDim.x + threadIdx.x;
    if (m >= BN_) return;
    int b = m >> 13;
    int cell = g_cellid[m];
    int p = b * N_ + g_cellstart[b * GC_ + cell] + g_rank[m];
    float x = xyz[(size_t)m * 3 + 0];
    float y = xyz[(size_t)m * 3 + 1];
    float z = xyz[(size_t)m * 3 + 2];
    g_pts4[p] = make_float4(x, y, z, 0.0f);
    g_pid[p] = m;
}

__global__ void sortfix_kernel() {
    int i = blockIdx.x * blockDim.x + threadIdx.x;
    if (i >= B_ * GC_) return;
    int b = i / GC_;
    int cell = i - b * GC_;
    int start = b * N_ + g_cellstart[b * GC_ + cell];
    int cnt = g_cellcnt[b * GC_ + cell];
    for (int a = 1; a < cnt; a++) {
        int pid = g_pid[start + a];
        float4 pt = g_pts4[start + a];
        int j = a - 1;
        while (j >= 0 && g_pid[start + j] > pid) {
            g_pid[start + j + 1]  = g_pid[start + j];
            g_pts4[start + j + 1] = g_pts4[start + j];
            j--;
        }
        g_pid[start + j + 1]  = pid;
        g_pts4[start + j + 1] = pt;
    }
    for (int a = 0; a < cnt; a++) g_spos[g_pid[start + a]] = start + a;
}

// ============================================================================
// Kernel: per-point preprocessing (EP/EQ/V), written in SORTED order.
// ============================================================================
#define PREP_SMEM ((3 * DPRE * C_ + 4 * 4 * 68) * 4)

__global__ void prep_kernel(const float* __restrict__ feat,
                            const float* __restrict__ xyz,
                            const float* __restrict__ Wr,
                            const float* __restrict__ br,
                            const float* __restrict__ Wv,
                            const float* __restrict__ bv) {
    extern __shared__ float sm[];
    float* sWA = sm;                       // Wr_left   [d][c]
    float* sWB = sm + DPRE * C_;           // Wr_right  [d][c] (then -= left)
    float* sWC = sm + 2 * DPRE * C_;       // Wv        [d][c]
    float* sPre = sm + 3 * DPRE * C_;      // [warp][4][68]

    int t = threadIdx.x;
    for (int i = t; i < C_ * 134; i += 128) {
        int c = i / 134, dd = i % 134;
        float v = Wr[i];
        if (dd < DPRE) sWA[dd * C_ + c] = v;
        else           sWB[(dd - DPRE) * C_ + c] = v;
    }
    for (int i = t; i < C_ * DPRE; i += 128) {
        int c = i / DPRE, d = i % DPRE;
        sWC[d * C_ + c] = Wv[i];
    }
    __syncthreads();
    for (int i = t; i < DPRE * C_; i += 128) sWB[i] -= sWA[i];
    __syncthreads();

    int w = t >> 5, lane = t & 31;
    float4 br4 = *(const float4*)&br[4 * lane];
    float4 bv4 = *(const float4*)&bv[4 * lane];
    float* spw = sPre + w * 4 * 68;

    int base = blockIdx.x * 128 + w * 32;   // 32 points per warp
    for (int it = 0; it < 8; it++) {
        int m0 = base + it * 4;
        #pragma unroll
        for (int p = 0; p < 4; p++) {
            int m = m0 + p;
            spw[p * 68 + lane]      = feat[(size_t)m * 64 + lane];
            spw[p * 68 + 32 + lane] = feat[(size_t)m * 64 + 32 + lane];
            if (lane < 3) spw[p * 68 + 64 + lane] = xyz[(size_t)m * 3 + lane];
        }
        __syncwarp();

        float aP[4][4], aQ[4][4], aV[4][4];
        #pragma unroll
        for (int p = 0; p < 4; p++)
            #pragma unroll
            for (int r = 0; r < 4; r++) { aP[p][r] = 0.f; aQ[p][r] = 0.f; aV[p][r] = 0.f; }

        for (int d = 0; d < DPRE; d++) {
            float4 wa = *(float4*)&sWA[d * C_ + 4 * lane];
            float4 wb = *(float4*)&sWB[d * C_ + 4 * lane];
            float4 wc = *(float4*)&sWC[d * C_ + 4 * lane];
            #pragma unroll
            for (int p = 0; p < 4; p++) {
                float x = spw[p * 68 + d];
                aP[p][0] = fmaf(wa.x, x, aP[p][0]);
                aP[p][1] = fmaf(wa.y, x, aP[p][1]);
                aP[p][2] = fmaf(wa.z, x, aP[p][2]);
                aP[p][3] = fmaf(wa.w, x, aP[p][3]);
                aQ[p][0] = fmaf(wb.x, x, aQ[p][0]);
                aQ[p][1] = fmaf(wb.y, x, aQ[p][1]);
                aQ[p][2] = fmaf(wb.z, x, aQ[p][2]);
                aQ[p][3] = fmaf(wb.w, x, aQ[p][3]);
                aV[p][0] = fmaf(wc.x, x, aV[p][0]);
                aV[p][1] = fmaf(wc.y, x, aV[p][1]);
                aV[p][2] = fmaf(wc.z, x, aV[p][2]);
                aV[p][3] = fmaf(wc.w, x, aV[p][3]);
            }
        }
        #pragma unroll
        for (int p = 0; p < 4; p++) {
            size_t sp = (size_t)g_spos[m0 + p];     // sorted destination
            float4 ep, eq, vv;
            ep.x = fast_exp(aP[p][0]); ep.y = fast_exp(aP[p][1]);
            ep.z = fast_exp(aP[p][2]); ep.w = fast_exp(aP[p][3]);
            eq.x = fast_exp(aQ[p][0] + br4.x); eq.y = fast_exp(aQ[p][1] + br4.y);
            eq.z = fast_exp(aQ[p][2] + br4.z); eq.w = fast_exp(aQ[p][3] + br4.w);
            vv.x = fmaxf(aV[p][0] + bv4.x, 0.f); vv.y = fmaxf(aV[p][1] + bv4.y, 0.f);
            vv.z = fmaxf(aV[p][2] + bv4.z, 0.f); vv.w = fmaxf(aV[p][3] + bv4.w, 0.f);
            *(float4*)&g_EP[sp * C_ + 4 * lane] = ep;
            *(float4*)&g_EQ[sp * C_ + 4 * lane] = eq;
            *(float4*)&g_V [sp * C_ + 4 * lane] = vv;
        }
        __syncwarp();
    }
}

// ============================================================================
// Kernel: exact 36-NN, WARP PER QUERY.
//  - half-warp column pairing: lanes 0-15 scan column (ix,iy0), 16-31 scan
//    (ix,iy0+1), stride 16; per-pair lane rotation keeps per-lane load even.
//  - register top-10 per lane; 36-count certificate; wall-aware r0.
//  - merge: warp bisection on distance bits for T = 36th smallest, then
//    ballot compaction (d < T) + deterministic slot-major tie fill (d == T).
//  - query shuffle spreads wall/interior queries across blocks (balance).
// ============================================================================
#define LLEN 10
#define INFBITS 0x7f800000u

__global__ void knnq_kernel() {
    int lane = threadIdx.x & 31;
    int W = blockIdx.x * (blockDim.x >> 5) + (threadIdx.x >> 5);
    int q = ((W & 7) << 12) | (W >> 3);       // balance shuffle (bijective)
    int b = q >> 13;

    float4 me = g_pts4[q];
    float qx = me.x, qy = me.y, qz = me.z;
    int cx = min(G_ - 1, max(0, (int)(qx * (float)G_)));
    int cy = min(G_ - 1, max(0, (int)(qy * (float)G_)));
    int cz = min(G_ - 1, max(0, (int)(qz * (float)G_)));

    const float h = 1.0f / (float)G_;
    const int cbase = b * GC_;
    const int pbase = b * N_;

    int clip = ((cx < 2 || cx > G_ - 3) ? 1 : 0)
             + ((cy < 2 || cy > G_ - 3) ? 1 : 0)
             + ((cz < 2 || cz > G_ - 3) ? 1 : 0);
    int r0 = 2 + clip;

    unsigned ld[LLEN];
    int      lp[LLEN];
    float    dth = 1e9f;

    int hwarp = lane >> 4;      // which column of the pair
    int lj    = lane & 15;      // index within half-warp

    for (int r = r0; ; r++) {
        #pragma unroll
        for (int s = 0; s < LLEN; s++) { ld[s] = INFBITS; lp[s] = -1; }

        int lox = max(cx - r, 0), hix = min(cx + r, G_ - 1);
        int loy = max(cy - r, 0), hiy = min(cy + r, G_ - 1);
        int loz = max(cz - r, 0), hiz = min(cz + r, G_ - 1);

        float d1 = (lox > 0)      ? (qx - (float)lox * h)        : 1e9f;
        float d2 = (hix < G_ - 1) ? ((float)(hix + 1) * h - qx)  : 1e9f;
        float d3 = (loy > 0)      ? (qy - (float)loy * h)        : 1e9f;
        float d4 = (hiy < G_ - 1) ? ((float)(hiy + 1) * h - qy)  : 1e9f;
        float d5 = (loz > 0)      ? (qz - (float)loz * h)        : 1e9f;
        float d6 = (hiz < G_ - 1) ? ((float)(hiz + 1) * h - qz)  : 1e9f;
        float dmin = fminf(fminf(fminf(d1, d2), fminf(d3, d4)), fminf(d5, d6));
        dth = fminf(dmin * dmin, 1e9f);

        int cnt_near = 0;

        for (int ix = lox; ix <= hix; ix++) {
            int colbase = cbase + (ix * G_) * G_;
            for (int iy0 = loy; iy0 <= hiy; iy0 += 2) {
                int iy = iy0 + hwarp;
                int s0 = 0, len = 0;
                if (iy <= hiy) {
                    int cc = colbase + iy * G_;
                    s0  = g_cellstart[cc + loz];
                    len = g_cellstart[cc + hiz] + g_cellcnt[cc + hiz] - s0;
                }
                int base = pbase + s0;
                int rot = (ix * 3 + iy0 * 5) & 15;   // de-skew lane<->j mapping
                for (int j = ((lj - rot) & 15); j < len; j += 16) {
                    float4 c = g_pts4[base + j];
                    float dx = c.x - qx, dy = c.y - qy, dz = c.z - qz;
                    float d = fmaf(dz, dz, fmaf(dy, dy, dx * dx));
                    cnt_near += (d <= dth) ? 1 : 0;
                    unsigned db = __float_as_uint(d);
                    if (db < ld[LLEN - 1]) {
                        unsigned cd = db; int cp = base + j;
                        #pragma unroll
                        for (int s = 0; s < LLEN; s++) {
                            unsigned od = ld[s]; int op = lp[s];
                            if (cd < od) { ld[s] = cd; lp[s] = cp; cd = od; cp = op; }
                        }
                    }
                }
            }
        }

        unsigned tot = __reduce_add_sync(0xffffffffu, (unsigned)cnt_near);
        bool all = (lox == 0 && hix == G_ - 1 && loy == 0 && hiy == G_ - 1 &&
                    loz == 0 && hiz == G_ - 1);
        if (tot >= (unsigned)K_ || all) break;
    }

    // ---- merge: bisection for T = 36th smallest distance (as uint bits) ----
    unsigned lo = __reduce_min_sync(0xffffffffu, ld[0]);
    unsigned hi = __float_as_uint(fminf(dth, 4.0f));   // certificate: count(<=dth)>=36
    if (hi < lo) hi = lo;
    int iter = 0;
    while (lo < hi && iter < 34) {
        unsigned mid = lo + ((hi - lo) >> 1);
        int c = 0;
        #pragma unroll
        for (int s = 0; s < LLEN; s++) c += (ld[s] <= mid) ? 1 : 0;
        unsigned tot = __reduce_add_sync(0xffffffffu, (unsigned)c);
        if (tot >= (unsigned)K_) hi = mid; else lo = mid + 1;
        iter++;
    }
    unsigned T = lo;

    // ---- compaction: all d < T, then fill to 36 with d == T (slot-major) ----
    unsigned lmlt = (1u << lane) - 1u;
    int base = 0;
    #pragma unroll
    for (int s = 0; s < LLEN; s++) {
        bool p = (ld[s] < T);
        unsigned m = __ballot_sync(0xffffffffu, p);
        if (p) g_nbr[(size_t)q * K_ + base + __popc(m & lmlt)] = lp[s];
        base += __popc(m);
    }
    #pragma unroll
    for (int s = 0; s < LLEN; s++) {
        if (base >= K_) break;                 // warp-uniform
        bool p = (ld[s] == T);
        unsigned m = __ballot_sync(0xffffffffu, p);
        int rk = __popc(m & lmlt);
        if (p && (base + rk) < K_) g_nbr[(size_t)q * K_ + base + rk] = lp[s];
        base += __popc(m);
    }
}

// ============================================================================
// Kernel: vector attention accumulate (R5 config: warp/query, 256 threads).
// ============================================================================
__global__ void attn_kernel() {
    int gw   = (blockIdx.x * blockDim.x + threadIdx.x) >> 5;
    int lane = threadIdx.x & 31;
    if (gw >= BN_) return;
    size_t q = (size_t)gw;

    float4 eq = *(const float4*)&g_EQ[q * C_ + 4 * lane];
    int i0 = g_nbr[q * K_ + lane];
    int i1 = (lane < K_ - 32) ? g_nbr[q * K_ + 32 + lane] : 0;

    float4 acc = make_float4(0.f, 0.f, 0.f, 0.f);
    #pragma unroll 4
    for (int k = 0; k < K_; k++) {
        int j = (k < 32) ? __shfl_sync(0xffffffffu, i0, k)
                         : __shfl_sync(0xffffffffu, i1, k - 32);
        float4 ep = *(const float4*)&g_EP[(size_t)j * C_ + 4 * lane];
        float4 v  = *(const float4*)&g_V [(size_t)j * C_ + 4 * lane];
        float wx = ep.x * eq.x, wy = ep.y * eq.y, wz = ep.z * eq.z, ww = ep.w * eq.w;
        float part = (wx + wy) + (wz + ww);
        part += __shfl_xor_sync(0xffffffffu, part, 16);
        part += __shfl_xor_sync(0xffffffffu, part, 8);
        part += __shfl_xor_sync(0xffffffffu, part, 4);
        part += __shfl_xor_sync(0xffffffffu, part, 2);
        part += __shfl_xor_sync(0xffffffffu, part, 1);
        float rinv = __fdividef(1.0f, part);
        acc.x = fmaf(v.x, wx * rinv, acc.x);
        acc.y = fmaf(v.y, wy * rinv, acc.y);
        acc.z = fmaf(v.z, wz * rinv, acc.z);
        acc.w = fmaf(v.w, ww * rinv, acc.w);
    }
    *(float4*)&g_mid[q * C_ + 4 * lane] = acc;
}

// ============================================================================
// Kernel: output projection  out[pid[q]] = mid[q] @ Ws^T + bs (R5 config).
// ============================================================================
#define WS_STRIDE 132
#define OUT_SMEM  ((C_ * WS_STRIDE + 8 * C_ * 9) * 4)

__global__ void outproj_kernel(const float* __restrict__ Ws,
                               const float* __restrict__ bs,
                               float* __restrict__ out) {
    extern __shared__ float sm[];
    float* sWs  = sm;                    // [c][d] stride WS_STRIDE
    float* sMid = sm + C_ * WS_STRIDE;   // [warp][c][9]

    int t = threadIdx.x, w = t >> 5, lane = t & 31;
    for (int i = t; i < C_ * C_; i += 256) {
        int d = i >> 7, c = i & 127;
        sWs[c * WS_STRIDE + d] = Ws[i];
    }
    __syncthreads();

    float4 bs4 = *(const float4*)&bs[4 * lane];
    float* smw = sMid + w * C_ * 9;
    int gw = blockIdx.x * 8 + w;                 // 2048 warps total

    for (int itq = 0; itq < 2; itq++) {
        int q0 = (gw + itq * 2048) * 8;
        #pragma unroll
        for (int p = 0; p < 8; p++) {
            float4 m4 = *(const float4*)&g_mid[(size_t)(q0 + p) * C_ + 4 * lane];
            smw[(4 * lane + 0) * 9 + p] = m4.x;
            smw[(4 * lane + 1) * 9 + p] = m4.y;
            smw[(4 * lane + 2) * 9 + p] = m4.z;
            smw[(4 * lane + 3) * 9 + p] = m4.w;
        }
        __syncwarp();
        float4 acc[8];
        #pragma unroll
        for (int p = 0; p < 8; p++) acc[p] = bs4;
        for (int c = 0; c < C_; c++) {
            float4 wr = *(float4*)&sWs[c * WS_STRIDE + 4 * lane];
            #pragma unroll
            for (int p = 0; p < 8; p++) {
                float mc = smw[c * 9 + p];
                acc[p].x = fmaf(wr.x, mc, acc[p].x);
                acc[p].y = fmaf(wr.y, mc, acc[p].y);
                acc[p].z = fmaf(wr.z, mc, acc[p].z);
                acc[p].w = fmaf(wr.w, mc, acc[p].w);
            }
        }
        #pragma unroll
        for (int p = 0; p < 8; p++) {
            size_t row = (size_t)g_pid[q0 + p];     // back to original order
            *(float4*)&out[row * C_ + 4 * lane] = acc[p];
        }
        __syncwarp();
    }
}

// ============================================================================
extern "C" void kernel_launch(void* const* d_in, const int* in_sizes, int n_in,
                              void* d_out, int out_size) {
    const float* feat = (const float*)d_in[0];
    const float* xyz  = (const float*)d_in[1];
    const float* Wr   = (const float*)d_in[2];
    const float* br   = (const float*)d_in[3];
    const float* Wv   = (const float*)d_in[4];
    const float* bv   = (const float*)d_in[5];
    const float* Ws   = (const float*)d_in[6];
    const float* bs   = (const float*)d_in[7];
    float* out = (float*)d_out;

    cudaFuncSetAttribute(prep_kernel, cudaFuncAttributeMaxDynamicSharedMemorySize, PREP_SMEM);
    cudaFuncSetAttribute(outproj_kernel, cudaFuncAttributeMaxDynamicSharedMemorySize, OUT_SMEM);

    void* ccnt;
    cudaGetSymbolAddress(&ccnt, g_cellcnt);
    cudaMemsetAsync(ccnt, 0, B_ * GC_ * sizeof(int));

    // grid build (R5 pipeline)
    cellassign_kernel<<<BN_ / 256, 256>>>(xyz);
    scan_kernel<<<B_, 1024>>>();
    scatter_kernel<<<BN_ / 256, 256>>>(xyz);
    sortfix_kernel<<<B_ * GC_ / 256, 256>>>();

    // per-point EP/EQ/V (written in sorted order)
    prep_kernel<<<BN_ / 128, 128, PREP_SMEM>>>(feat, xyz, Wr, br, Wv, bv);

    // exact 36-NN, warp per query (paired columns + bisection merge)
    knnq_kernel<<<BN_ / 8, 256>>>();

    // vector attention accumulate
    attn_kernel<<<BN_ / 8, 256>>>();

    // output projection (+ scatter back to original order)
    outproj_kernel<<<256, 256, OUT_SMEM>>>(Ws, bs, out);
}